// round 8
// baseline (speedup 1.0000x reference)
#include <cuda_runtime.h>

// ---------------------------------------------------------------------------
// 2-layer tanh RNN, persistent-CTA scan kernels with global spin barriers.
// Shapes: VOCAB=25, HIDDEN=512, OUT=1000, BATCH=64, SEQ=512.
//
// prep:  zero barriers + decode token ids (auto-detect int32 vs int64, clamp).
// scan1: layer-1 recurrence, 128 persistent CTAs, W_hh0 + W_ih1 slices
//        SMEM-resident; the layer-1 -> layer-2 projection is folded into the
//        same step (h1[t-1] is already staged in SMEM).
// scan2: layer-2 recurrence over xw1 (biases pre-folded).
// outk:  out = h2[:,511,:] @ W_out^T + b_out.
// ---------------------------------------------------------------------------

#define SEQ_T 512
#define HID   512
#define BAT   64
#define VOC   25
#define NOUT  1000
#define NCTA  128     // CTAs per scan (<= SM count, guaranteed co-resident)
#define NT    256     // threads per CTA
#define HB    (HID*BAT)   // 32768

// Scratch (append-only per timestep => no cross-SM L1 staleness hazard)
__device__ float g_h1 [SEQ_T * HB];   // layer-1 hidden history [t][j][b]
__device__ float g_xw1[SEQ_T * HB];   // projected input to layer 2 [t][o][b]
__device__ float g_h2 [SEQ_T * HB];   // layer-2 hidden history [t][j][b]
__device__ int   g_bar[2 * SEQ_T];    // grid-barrier counters
__device__ int   g_x  [BAT * SEQ_T];  // decoded, clamped token ids

extern __shared__ float smem[];

__device__ __forceinline__ int ld_vol(const int* p) {
    int v;
    asm volatile("ld.volatile.global.s32 %0, [%1];" : "=r"(v) : "l"(p));
    return v;
}

// All-CTA barrier: producer fence + atomic arrive, thread 0 spins, block sync.
__device__ __forceinline__ void grid_bar(int* bar, int n) {
    __syncthreads();
    if (threadIdx.x == 0) {
        __threadfence();
        atomicAdd(bar, 1);
        while (ld_vol(bar) < n) { }
        __threadfence();
    }
    __syncthreads();
}

// ---------------------------------------------------------------------------
// Prep: zero barriers; decode x. If x is int64 (little-endian, values 0..24),
// every odd int32 word is 0. For real int32 tokens, P(64 odd words all 0)
// ~ (1/25)^64 ~ 0. Only reads BAT*SEQ_T int32 words => safe for both dtypes.
// ---------------------------------------------------------------------------
__global__ void prep_kernel(const int* __restrict__ xr) {
    __shared__ int s_is64;
    const int tid = threadIdx.x;
    if (tid < 2 * SEQ_T) g_bar[tid] = 0;   // 2*SEQ_T == 1024 == blockDim
    if (tid == 0) {
        int odd_or = 0;
        #pragma unroll
        for (int i = 1; i < 128; i += 2) odd_or |= xr[i];
        s_is64 = (odd_or == 0);
    }
    __syncthreads();
    const bool i64 = (s_is64 != 0);
    for (int i = tid; i < BAT * SEQ_T; i += 1024) {
        int v = i64 ? (int)((const long long*)xr)[i] : xr[i];
        v = min(max(v, 0), VOC - 1);       // clamp: never fault on surprises
        g_x[i] = v;
    }
}

// ---------------------------------------------------------------------------
// Layer-1 scan + folded projection.
// smem: hs[HID][BAT] (128KB) | wrec[4][HID] | wproj[4][HID] | esm[4][32]
// thread -> (il = tid>>6 in 0..3, b = tid&63); output row i = blk*4 + il.
// ---------------------------------------------------------------------------
__global__ void __launch_bounds__(NT, 1) scan1_kernel(
    const float* __restrict__ W_ih0,      // [HID][VOC]
    const float* __restrict__ b_ih0,      // [HID]
    const float* __restrict__ b_hh0,      // [HID]
    const float* __restrict__ W_hh0,      // [HID][HID]
    const float* __restrict__ W_ih1,      // [HID][HID]
    const float* __restrict__ b_ih1,      // [HID]
    const float* __restrict__ b_hh1)      // [HID]
{
    float* hs    = smem;                  // [HID][BAT]
    float* wrec  = smem + HB;             // [4][HID]
    float* wproj = wrec + 4 * HID;        // [4][HID]
    float* esm   = wproj + 4 * HID;       // [4][32]  embedding (biases folded)

    const int tid = threadIdx.x;
    const int il  = tid >> 6;
    const int b   = tid & 63;
    const int i0  = blockIdx.x * 4;

    // Stage stationary weights for this CTA's slice.
    for (int k = tid; k < 4 * HID; k += NT) {
        int r = k >> 9, c = k & (HID - 1);
        wrec[k]  = W_hh0[(i0 + r) * HID + c];
        wproj[k] = W_ih1[(i0 + r) * HID + c];
    }
    // Embedding rows for this slice, with b_ih0 + b_hh0 folded in.
    for (int k = tid; k < 4 * 32; k += NT) {
        int r = k >> 5, v = k & 31;
        float e = 0.f;
        if (v < VOC) e = W_ih0[(i0 + r) * VOC + v] + b_ih0[i0 + r] + b_hh0[i0 + r];
        esm[k] = e;
    }
    const float bp = b_ih1[i0 + il] + b_hh1[i0 + il];  // fold both L2-input biases
    __syncthreads();

    const float* wr = wrec  + il * HID;
    const float* wp = wproj + il * HID;
    const int*   xb = g_x + b * SEQ_T;

    for (int t = 0; t < SEQ_T; t++) {
        float ar = 0.f;
        if (t > 0) {
            // Stage h1[t-1] (full hidden state) into SMEM, coalesced float4.
            const float4* src = (const float4*)(g_h1 + (t - 1) * HB);
            float4*       dst = (float4*)hs;
            #pragma unroll 8
            for (int m = 0; m < (HB / 4) / NT; m++)
                dst[tid + m * NT] = src[tid + m * NT];
            __syncthreads();

            float ap = 0.f;
            #pragma unroll 4
            for (int j = 0; j < HID; j += 4) {
                float4 w4 = *(const float4*)(wr + j);
                float4 p4 = *(const float4*)(wp + j);
                float h0  = hs[(j + 0) * BAT + b];
                float h1v = hs[(j + 1) * BAT + b];
                float h2v = hs[(j + 2) * BAT + b];
                float h3v = hs[(j + 3) * BAT + b];
                ar = fmaf(w4.x, h0, ar); ar = fmaf(w4.y, h1v, ar);
                ar = fmaf(w4.z, h2v, ar); ar = fmaf(w4.w, h3v, ar);
                ap = fmaf(p4.x, h0, ap); ap = fmaf(p4.y, h1v, ap);
                ap = fmaf(p4.z, h2v, ap); ap = fmaf(p4.w, h3v, ap);
            }
            // Projection of h1[t-1] -> layer-2 input (consumed only by the
            // next kernel launch; no barrier needed).
            g_xw1[(t - 1) * HB + (i0 + il) * BAT + b] = ap + bp;
        }
        int v = xb[t];
        float z = esm[il * 32 + v] + ar;
        float h = tanhf(z);
        g_h1[t * HB + (i0 + il) * BAT + b] = h;
        grid_bar(&g_bar[t], NCTA);
    }

    // Epilogue: projection of the final hidden state h1[T-1].
    {
        const float4* src = (const float4*)(g_h1 + (SEQ_T - 1) * HB);
        float4*       dst = (float4*)hs;
        #pragma unroll 8
        for (int m = 0; m < (HB / 4) / NT; m++)
            dst[tid + m * NT] = src[tid + m * NT];
        __syncthreads();
        float ap = 0.f;
        #pragma unroll 4
        for (int j = 0; j < HID; j += 4) {
            float4 p4 = *(const float4*)(wp + j);
            ap = fmaf(p4.x, hs[(j + 0) * BAT + b], ap);
            ap = fmaf(p4.y, hs[(j + 1) * BAT + b], ap);
            ap = fmaf(p4.z, hs[(j + 2) * BAT + b], ap);
            ap = fmaf(p4.w, hs[(j + 3) * BAT + b], ap);
        }
        g_xw1[(SEQ_T - 1) * HB + (i0 + il) * BAT + b] = ap + bp;
    }
}

// ---------------------------------------------------------------------------
// Layer-2 scan. Same structure, xt comes from g_xw1 (biases already folded).
// ---------------------------------------------------------------------------
__global__ void __launch_bounds__(NT, 1) scan2_kernel(
    const float* __restrict__ W_hh1)      // [HID][HID]
{
    float* hs   = smem;                   // [HID][BAT]
    float* wrec = smem + HB;              // [4][HID]

    const int tid = threadIdx.x;
    const int il  = tid >> 6;
    const int b   = tid & 63;
    const int i0  = blockIdx.x * 4;

    for (int k = tid; k < 4 * HID; k += NT) {
        int r = k >> 9, c = k & (HID - 1);
        wrec[k] = W_hh1[(i0 + r) * HID + c];
    }
    __syncthreads();

    const float* wr = wrec + il * HID;

    for (int t = 0; t < SEQ_T; t++) {
        float ar = 0.f;
        if (t > 0) {
            const float4* src = (const float4*)(g_h2 + (t - 1) * HB);
            float4*       dst = (float4*)hs;
            #pragma unroll 8
            for (int m = 0; m < (HB / 4) / NT; m++)
                dst[tid + m * NT] = src[tid + m * NT];
            __syncthreads();
            #pragma unroll 4
            for (int j = 0; j < HID; j += 4) {
                float4 w4 = *(const float4*)(wr + j);
                ar = fmaf(w4.x, hs[(j + 0) * BAT + b], ar);
                ar = fmaf(w4.y, hs[(j + 1) * BAT + b], ar);
                ar = fmaf(w4.z, hs[(j + 2) * BAT + b], ar);
                ar = fmaf(w4.w, hs[(j + 3) * BAT + b], ar);
            }
        }
        float z = g_xw1[t * HB + (i0 + il) * BAT + b] + ar;
        float h = tanhf(z);
        g_h2[t * HB + (i0 + il) * BAT + b] = h;
        grid_bar(&g_bar[SEQ_T + t], NCTA);
    }
}

// ---------------------------------------------------------------------------
// Output: out[b][o] = sum_h W_out[o][h] * h2[T-1][h][b] + b_out[o].
// 250 CTAs x 4 output rows.
// ---------------------------------------------------------------------------
__global__ void __launch_bounds__(NT) out_kernel(
    const float* __restrict__ W_out,      // [NOUT][HID]
    const float* __restrict__ b_out,      // [NOUT]
    float* __restrict__ out)              // [BAT][NOUT]
{
    float* hs  = smem;                    // [HID][BAT]
    float* wsm = smem + HB;               // [4][HID]

    const int tid = threadIdx.x;
    const int il  = tid >> 6;
    const int b   = tid & 63;
    const int o0  = blockIdx.x * 4;

    for (int k = tid; k < 4 * HID; k += NT) {
        int r = k >> 9, c = k & (HID - 1);
        wsm[k] = W_out[(o0 + r) * HID + c];
    }
    {
        const float4* src = (const float4*)(g_h2 + (SEQ_T - 1) * HB);
        float4*       dst = (float4*)hs;
        #pragma unroll 8
        for (int m = 0; m < (HB / 4) / NT; m++)
            dst[tid + m * NT] = src[tid + m * NT];
    }
    __syncthreads();

    const float* wr = wsm + il * HID;
    float ar = 0.f;
    #pragma unroll 4
    for (int j = 0; j < HID; j += 4) {
        float4 w4 = *(const float4*)(wr + j);
        ar = fmaf(w4.x, hs[(j + 0) * BAT + b], ar);
        ar = fmaf(w4.y, hs[(j + 1) * BAT + b], ar);
        ar = fmaf(w4.z, hs[(j + 2) * BAT + b], ar);
        ar = fmaf(w4.w, hs[(j + 3) * BAT + b], ar);
    }
    out[b * NOUT + (o0 + il)] = ar + b_out[o0 + il];
}

// ---------------------------------------------------------------------------
extern "C" void kernel_launch(void* const* d_in, const int* in_sizes, int n_in,
                              void* d_out, int out_size)
{
    const int*   x_raw     = (const int*)d_in[0];   // int32 OR int64 (auto-detect)
    const float* W_ih0     = (const float*)d_in[1];
    const float* W_hh0     = (const float*)d_in[2];
    const float* b_ih0     = (const float*)d_in[3];
    const float* b_hh0     = (const float*)d_in[4];
    const float* W_ih1     = (const float*)d_in[5];
    const float* W_hh1     = (const float*)d_in[6];
    const float* b_ih1     = (const float*)d_in[7];
    const float* b_hh1     = (const float*)d_in[8];
    const float* W_out     = (const float*)d_in[9];
    const float* b_out     = (const float*)d_in[10];
    float* out             = (float*)d_out;

    const size_t s1 = (size_t)(HB + 8 * HID + 128) * sizeof(float);  // 147968
    const size_t s2 = (size_t)(HB + 4 * HID) * sizeof(float);        // 139264
    const size_t s3 = s2;

    cudaFuncSetAttribute(scan1_kernel, cudaFuncAttributeMaxDynamicSharedMemorySize, (int)s1);
    cudaFuncSetAttribute(scan2_kernel, cudaFuncAttributeMaxDynamicSharedMemorySize, (int)s2);
    cudaFuncSetAttribute(out_kernel,   cudaFuncAttributeMaxDynamicSharedMemorySize, (int)s3);

    prep_kernel<<<1, 1024>>>(x_raw);
    scan1_kernel<<<NCTA, NT, s1>>>(W_ih0, b_ih0, b_hh0, W_hh0, W_ih1, b_ih1, b_hh1);
    scan2_kernel<<<NCTA, NT, s2>>>(W_hh1);
    out_kernel<<<(NOUT + 3) / 4, NT, s3>>>(W_out, b_out, out);
}

// round 13
// speedup vs baseline: 1.3339x; 1.3339x over previous
#include <cuda_runtime.h>

// ---------------------------------------------------------------------------
// 2-layer tanh RNN, persistent-CTA scan kernels with global spin barriers.
// Shapes: VOCAB=25, HIDDEN=512, OUT=1000, BATCH=64, SEQ=512.
//
// R8: packed fma.rn.f32x2 (halves FFMA issue count), NT=128 with 2 rows per
//     thread (halves smem crossbar traffic), cp.async.cg 4-chunk pipelined
//     staging of h (overlaps the 16MB/step L2 broadcast with compute).
// ---------------------------------------------------------------------------

#define SEQ_T 512
#define HID   512
#define BAT   64
#define VOC   25
#define NOUT  1000
#define NCTA  128     // scan CTAs (1/SM, all co-resident)
#define NTS   128     // threads per scan CTA
#define NTO   256     // threads for out kernel
#define HB    (HID*BAT)   // 32768 floats = 128KB

// Scratch (append-only per timestep => no cross-SM staleness hazard)
__device__ float g_h1 [SEQ_T * HB];
__device__ float g_xw1[SEQ_T * HB];
__device__ float g_h2 [SEQ_T * HB];
__device__ int   g_bar[2 * SEQ_T];
__device__ int   g_x  [BAT * SEQ_T];

extern __shared__ float smem[];

typedef unsigned long long ull;

// ---- packed f32x2 helpers -------------------------------------------------
__device__ __forceinline__ ull pk2(float a, float b) {
    ull r;
    asm("mov.b64 %0, {%1, %2};" : "=l"(r)
        : "r"(__float_as_uint(a)), "r"(__float_as_uint(b)));
    return r;
}
__device__ __forceinline__ void fma2(ull& d, ull a, ull b) {
    asm("fma.rn.f32x2 %0, %1, %2, %0;" : "+l"(d) : "l"(a), "l"(b));
}
__device__ __forceinline__ float fold2(ull v) {
    unsigned int x, y;
    asm("mov.b64 {%0, %1}, %2;" : "=r"(x), "=r"(y) : "l"(v));
    return __uint_as_float(x) + __uint_as_float(y);
}

// ---- cp.async helpers -----------------------------------------------------
__device__ __forceinline__ void cpa16(unsigned int dst, const void* src) {
    asm volatile("cp.async.cg.shared.global [%0], [%1], 16;" :: "r"(dst), "l"(src));
}
#define CPA_COMMIT() asm volatile("cp.async.commit_group;")
#define CPA_WAIT(n)  asm volatile("cp.async.wait_group %0;" :: "n"(n))

// ---- grid barrier ---------------------------------------------------------
__device__ __forceinline__ int ld_vol(const int* p) {
    int v;
    asm volatile("ld.volatile.global.s32 %0, [%1];" : "=r"(v) : "l"(p));
    return v;
}
__device__ __forceinline__ void grid_bar(int* bar, int n) {
    __syncthreads();
    if (threadIdx.x == 0) {
        __threadfence();
        atomicAdd(bar, 1);
        while (ld_vol(bar) < n) { }
        __threadfence();
    }
    __syncthreads();
}

// ---------------------------------------------------------------------------
// Prep: zero barriers; decode x (auto-detect int32 vs int64; clamp).
// ---------------------------------------------------------------------------
__global__ void prep_kernel(const int* __restrict__ xr) {
    __shared__ int s_is64;
    const int tid = threadIdx.x;
    if (tid < 2 * SEQ_T) g_bar[tid] = 0;
    if (tid == 0) {
        int odd_or = 0;
        #pragma unroll
        for (int i = 1; i < 128; i += 2) odd_or |= xr[i];
        s_is64 = (odd_or == 0);
    }
    __syncthreads();
    const bool i64 = (s_is64 != 0);
    for (int i = tid; i < BAT * SEQ_T; i += 1024) {
        int v = i64 ? (int)((const long long*)xr)[i] : xr[i];
        g_x[i] = min(max(v, 0), VOC - 1);
    }
}

// ---------------------------------------------------------------------------
// Layer-1 scan + folded layer-2 input projection.
// smem: hs[512][64] | wrec[4][512] | wproj[4][512] | esm[4][32]
// thread -> g = tid>>6 (row pair), b = tid&63. Rows: i0+2g, i0+2g+1.
// Accumulators packed over j-parity (f32x2), folded at step end.
// ---------------------------------------------------------------------------
__global__ void __launch_bounds__(NTS, 1) scan1_kernel(
    const float* __restrict__ W_ih0,      // [HID][VOC]
    const float* __restrict__ b_ih0,
    const float* __restrict__ b_hh0,
    const float* __restrict__ W_hh0,      // [HID][HID]
    const float* __restrict__ W_ih1,      // [HID][HID]
    const float* __restrict__ b_ih1,
    const float* __restrict__ b_hh1)
{
    float* hs    = smem;                  // [512][64]
    float* wrec  = smem + HB;             // [4][512]
    float* wproj = wrec + 4 * HID;        // [4][512]
    float* esm   = wproj + 4 * HID;       // [4][32]

    const int tid = threadIdx.x;
    const int g   = tid >> 6;             // 0..1
    const int b   = tid & 63;
    const int i0  = blockIdx.x * 4;
    const int r0  = 2 * g, r1 = 2 * g + 1;

    for (int k = tid; k < 4 * HID; k += NTS) {
        int r = k >> 9, c = k & (HID - 1);
        wrec[k]  = W_hh0[(i0 + r) * HID + c];
        wproj[k] = W_ih1[(i0 + r) * HID + c];
    }
    {   // embedding rows with b_ih0 + b_hh0 folded (128 entries, 128 threads)
        int r = tid >> 5, v = tid & 31;
        float e = 0.f;
        if (v < VOC) e = W_ih0[(i0 + r) * VOC + v] + b_ih0[i0 + r] + b_hh0[i0 + r];
        esm[tid] = e;
    }
    const float bp0 = b_ih1[i0 + r0] + b_hh1[i0 + r0];
    const float bp1 = b_ih1[i0 + r1] + b_hh1[i0 + r1];
    __syncthreads();

    const float* wA = wrec  + r0 * HID;
    const float* wB = wrec  + r1 * HID;
    const float* pA = wproj + r0 * HID;
    const float* pB = wproj + r1 * HID;
    const unsigned int hs_u = (unsigned int)__cvta_generic_to_shared(hs) + tid * 16;
    const int* xb = g_x + b * SEQ_T;

    for (int t = 0; t < SEQ_T; t++) {
        const int v = xb[t];
        float a0 = 0.f, a1 = 0.f;
        if (t > 0) {
            // Issue all 4 chunk copies (32KB each) immediately; pipeline below.
            const char* gsrc = (const char*)(g_h1 + (t - 1) * HB) + tid * 16;
            #pragma unroll
            for (int c = 0; c < 4; c++) {
                #pragma unroll
                for (int k = 0; k < 16; k++)
                    cpa16(hs_u + c * 32768 + k * 2048, gsrc + c * 32768 + k * 2048);
                CPA_COMMIT();
            }
            ull ar0 = 0, ar1 = 0, ap0 = 0, ap1 = 0;
            #pragma unroll
            for (int c = 0; c < 4; c++) {
                if      (c == 0) CPA_WAIT(3);
                else if (c == 1) CPA_WAIT(2);
                else if (c == 2) CPA_WAIT(1);
                else             CPA_WAIT(0);
                __syncthreads();
                const float* hc = hs + c * (128 * BAT);
                const float* wa = wA + c * 128;
                const float* wb = wB + c * 128;
                const float* pa = pA + c * 128;
                const float* pb = pB + c * 128;
                #pragma unroll 4
                for (int jj = 0; jj < 128; jj += 4) {
                    float h0 = hc[(jj + 0) * BAT + b];
                    float h1 = hc[(jj + 1) * BAT + b];
                    float h2 = hc[(jj + 2) * BAT + b];
                    float h3 = hc[(jj + 3) * BAT + b];
                    ull hA = pk2(h0, h1), hB = pk2(h2, h3);
                    ulonglong2 wav = *reinterpret_cast<const ulonglong2*>(wa + jj);
                    ulonglong2 wbv = *reinterpret_cast<const ulonglong2*>(wb + jj);
                    ulonglong2 pav = *reinterpret_cast<const ulonglong2*>(pa + jj);
                    ulonglong2 pbv = *reinterpret_cast<const ulonglong2*>(pb + jj);
                    fma2(ar0, wav.x, hA); fma2(ar0, wav.y, hB);
                    fma2(ar1, wbv.x, hA); fma2(ar1, wbv.y, hB);
                    fma2(ap0, pav.x, hA); fma2(ap0, pav.y, hB);
                    fma2(ap1, pbv.x, hA); fma2(ap1, pbv.y, hB);
                }
            }
            a0 = fold2(ar0);
            a1 = fold2(ar1);
            // Layer-2 input for step t-1 (consumed by the next launch only).
            g_xw1[(t - 1) * HB + (i0 + r0) * BAT + b] = fold2(ap0) + bp0;
            g_xw1[(t - 1) * HB + (i0 + r1) * BAT + b] = fold2(ap1) + bp1;
        }
        float z0 = esm[r0 * 32 + v] + a0;
        float z1 = esm[r1 * 32 + v] + a1;
        g_h1[t * HB + (i0 + r0) * BAT + b] = tanhf(z0);
        g_h1[t * HB + (i0 + r1) * BAT + b] = tanhf(z1);
        grid_bar(&g_bar[t], NCTA);
    }

    // Epilogue: projection of h1[T-1].
    {
        const float4* src = (const float4*)(g_h1 + (SEQ_T - 1) * HB);
        float4*       dst = (float4*)hs;
        #pragma unroll 8
        for (int m = 0; m < (HB / 4) / NTS; m++)
            dst[tid + m * NTS] = src[tid + m * NTS];
        __syncthreads();
        ull ap0 = 0, ap1 = 0;
        #pragma unroll 4
        for (int j = 0; j < HID; j += 4) {
            float h0 = hs[(j + 0) * BAT + b];
            float h1 = hs[(j + 1) * BAT + b];
            float h2 = hs[(j + 2) * BAT + b];
            float h3 = hs[(j + 3) * BAT + b];
            ull hA = pk2(h0, h1), hB = pk2(h2, h3);
            ulonglong2 pav = *reinterpret_cast<const ulonglong2*>(pA + j);
            ulonglong2 pbv = *reinterpret_cast<const ulonglong2*>(pB + j);
            fma2(ap0, pav.x, hA); fma2(ap0, pav.y, hB);
            fma2(ap1, pbv.x, hA); fma2(ap1, pbv.y, hB);
        }
        g_xw1[(SEQ_T - 1) * HB + (i0 + r0) * BAT + b] = fold2(ap0) + bp0;
        g_xw1[(SEQ_T - 1) * HB + (i0 + r1) * BAT + b] = fold2(ap1) + bp1;
    }
}

// ---------------------------------------------------------------------------
// Layer-2 scan. Same structure, xt = g_xw1[t] (biases pre-folded).
// ---------------------------------------------------------------------------
__global__ void __launch_bounds__(NTS, 1) scan2_kernel(
    const float* __restrict__ W_hh1)
{
    float* hs   = smem;                   // [512][64]
    float* wrec = smem + HB;              // [4][512]

    const int tid = threadIdx.x;
    const int g   = tid >> 6;
    const int b   = tid & 63;
    const int i0  = blockIdx.x * 4;
    const int r0  = 2 * g, r1 = 2 * g + 1;

    for (int k = tid; k < 4 * HID; k += NTS) {
        int r = k >> 9, c = k & (HID - 1);
        wrec[k] = W_hh1[(i0 + r) * HID + c];
    }
    __syncthreads();

    const float* wA = wrec + r0 * HID;
    const float* wB = wrec + r1 * HID;
    const unsigned int hs_u = (unsigned int)__cvta_generic_to_shared(hs) + tid * 16;

    for (int t = 0; t < SEQ_T; t++) {
        // Prefetch this step's inputs early (hides L2/DRAM latency).
        const float xa0 = g_xw1[t * HB + (i0 + r0) * BAT + b];
        const float xa1 = g_xw1[t * HB + (i0 + r1) * BAT + b];
        float a0 = 0.f, a1 = 0.f;
        if (t > 0) {
            const char* gsrc = (const char*)(g_h2 + (t - 1) * HB) + tid * 16;
            #pragma unroll
            for (int c = 0; c < 4; c++) {
                #pragma unroll
                for (int k = 0; k < 16; k++)
                    cpa16(hs_u + c * 32768 + k * 2048, gsrc + c * 32768 + k * 2048);
                CPA_COMMIT();
            }
            ull ar0 = 0, ar1 = 0;
            #pragma unroll
            for (int c = 0; c < 4; c++) {
                if      (c == 0) CPA_WAIT(3);
                else if (c == 1) CPA_WAIT(2);
                else if (c == 2) CPA_WAIT(1);
                else             CPA_WAIT(0);
                __syncthreads();
                const float* hc = hs + c * (128 * BAT);
                const float* wa = wA + c * 128;
                const float* wb = wB + c * 128;
                #pragma unroll 4
                for (int jj = 0; jj < 128; jj += 4) {
                    float h0 = hc[(jj + 0) * BAT + b];
                    float h1 = hc[(jj + 1) * BAT + b];
                    float h2 = hc[(jj + 2) * BAT + b];
                    float h3 = hc[(jj + 3) * BAT + b];
                    ull hA = pk2(h0, h1), hB = pk2(h2, h3);
                    ulonglong2 wav = *reinterpret_cast<const ulonglong2*>(wa + jj);
                    ulonglong2 wbv = *reinterpret_cast<const ulonglong2*>(wb + jj);
                    fma2(ar0, wav.x, hA); fma2(ar0, wav.y, hB);
                    fma2(ar1, wbv.x, hA); fma2(ar1, wbv.y, hB);
                }
            }
            a0 = fold2(ar0);
            a1 = fold2(ar1);
        }
        g_h2[t * HB + (i0 + r0) * BAT + b] = tanhf(xa0 + a0);
        g_h2[t * HB + (i0 + r1) * BAT + b] = tanhf(xa1 + a1);
        grid_bar(&g_bar[SEQ_T + t], NCTA);
    }
}

// ---------------------------------------------------------------------------
// Output: out[b][o] = sum_h W_out[o][h] * h2[T-1][h][b] + b_out[o].
// ---------------------------------------------------------------------------
__global__ void __launch_bounds__(NTO) out_kernel(
    const float* __restrict__ W_out,
    const float* __restrict__ b_out,
    float* __restrict__ out)
{
    float* hs  = smem;                    // [512][64]
    float* wsm = smem + HB;               // [4][512]

    const int tid = threadIdx.x;
    const int il  = tid >> 6;
    const int b   = tid & 63;
    const int o0  = blockIdx.x * 4;

    for (int k = tid; k < 4 * HID; k += NTO) {
        int r = k >> 9, c = k & (HID - 1);
        wsm[k] = W_out[(o0 + r) * HID + c];
    }
    {
        const float4* src = (const float4*)(g_h2 + (SEQ_T - 1) * HB);
        float4*       dst = (float4*)hs;
        #pragma unroll 8
        for (int m = 0; m < (HB / 4) / NTO; m++)
            dst[tid + m * NTO] = src[tid + m * NTO];
    }
    __syncthreads();

    const float* wr = wsm + il * HID;
    float ar = 0.f;
    #pragma unroll 4
    for (int j = 0; j < HID; j += 4) {
        float4 w4 = *(const float4*)(wr + j);
        ar = fmaf(w4.x, hs[(j + 0) * BAT + b], ar);
        ar = fmaf(w4.y, hs[(j + 1) * BAT + b], ar);
        ar = fmaf(w4.z, hs[(j + 2) * BAT + b], ar);
        ar = fmaf(w4.w, hs[(j + 3) * BAT + b], ar);
    }
    out[b * NOUT + (o0 + il)] = ar + b_out[o0 + il];
}

// ---------------------------------------------------------------------------
extern "C" void kernel_launch(void* const* d_in, const int* in_sizes, int n_in,
                              void* d_out, int out_size)
{
    const int*   x_raw = (const int*)d_in[0];   // int32 OR int64 (auto-detect)
    const float* W_ih0 = (const float*)d_in[1];
    const float* W_hh0 = (const float*)d_in[2];
    const float* b_ih0 = (const float*)d_in[3];
    const float* b_hh0 = (const float*)d_in[4];
    const float* W_ih1 = (const float*)d_in[5];
    const float* W_hh1 = (const float*)d_in[6];
    const float* b_ih1 = (const float*)d_in[7];
    const float* b_hh1 = (const float*)d_in[8];
    const float* W_out = (const float*)d_in[9];
    const float* b_out = (const float*)d_in[10];
    float* out         = (float*)d_out;

    const size_t s1 = (size_t)(HB + 8 * HID + 128) * sizeof(float);  // 147968
    const size_t s2 = (size_t)(HB + 4 * HID) * sizeof(float);        // 139264
    const size_t s3 = s2;

    cudaFuncSetAttribute(scan1_kernel, cudaFuncAttributeMaxDynamicSharedMemorySize, (int)s1);
    cudaFuncSetAttribute(scan2_kernel, cudaFuncAttributeMaxDynamicSharedMemorySize, (int)s2);
    cudaFuncSetAttribute(out_kernel,   cudaFuncAttributeMaxDynamicSharedMemorySize, (int)s3);

    prep_kernel<<<1, 1024>>>(x_raw);
    scan1_kernel<<<NCTA, NTS, s1>>>(W_ih0, b_ih0, b_hh0, W_hh0, W_ih1, b_ih1, b_hh1);
    scan2_kernel<<<NCTA, NTS, s2>>>(W_hh1);
    out_kernel<<<(NOUT + 3) / 4, NTO, s3>>>(W_out, b_out, out);
}

// round 14
// speedup vs baseline: 1.6322x; 1.2236x over previous
#include <cuda_runtime.h>

// ---------------------------------------------------------------------------
// 2-layer tanh RNN — single merged persistent kernel, layer-pipelined.
// Shapes: VOCAB=25, HIDDEN=512, OUT=1000, BATCH=64, SEQ=512.
//
// R13: merge scan1+scan2 into ONE kernel: CTAs 0..63 run layer-1 (8 rows of
//      W_hh0 + W_ih1, rec + folded projection per round), CTAs 64..127 run
//      layer-2 (8 rows of W_hh1) lagging one step, synchronized by per-round
//      counters (own class) and per-producer flags (xw1 slices). 1024 global
//      rounds -> 513; the two layers' compute and broadcasts fully overlap.
// ---------------------------------------------------------------------------

#define SEQ_T 512
#define HID   512
#define BAT   64
#define VOC   25
#define NOUT  1000
#define NL1   64          // layer-1 CTAs (and layer-2 CTAs)
#define NT    128         // threads per scan CTA
#define NTO   256         // threads for out kernel
#define HB    (HID*BAT)   // 32768 floats = 128KB

// Scratch (append-only per timestep => no cross-SM staleness hazard)
__device__ float g_h1 [SEQ_T * HB];
__device__ float g_xw1[SEQ_T * HB];
__device__ float g_h2 [SEQ_T * HB];
__device__ int   g_cnt1[SEQ_T];        // layer-1 round arrivals (64 each)
__device__ int   g_cnt2[SEQ_T];        // layer-2 round arrivals (64 each)
__device__ int   g_flagx[SEQ_T * NL1]; // xw1[t] slice ready, per producer CTA
__device__ int   g_x  [BAT * SEQ_T];

extern __shared__ float smem[];
typedef unsigned long long ull;

// ---- packed f32x2 helpers -------------------------------------------------
__device__ __forceinline__ ull pk2(float a, float b) {
    ull r;
    asm("mov.b64 %0, {%1, %2};" : "=l"(r)
        : "r"(__float_as_uint(a)), "r"(__float_as_uint(b)));
    return r;
}
__device__ __forceinline__ void fma2(ull& d, ull a, ull b) {
    asm("fma.rn.f32x2 %0, %1, %2, %0;" : "+l"(d) : "l"(a), "l"(b));
}
__device__ __forceinline__ float fold2(ull v) {
    unsigned int x, y;
    asm("mov.b64 {%0, %1}, %2;" : "=r"(x), "=r"(y) : "l"(v));
    return __uint_as_float(x) + __uint_as_float(y);
}

// ---- cp.async helpers -----------------------------------------------------
__device__ __forceinline__ void cpa16(unsigned int dst, const void* src) {
    asm volatile("cp.async.cg.shared.global [%0], [%1], 16;" :: "r"(dst), "l"(src));
}
#define CPA_COMMIT() asm volatile("cp.async.commit_group;")
#define CPA_WAIT(n)  asm volatile("cp.async.wait_group %0;" :: "n"(n))

__device__ __forceinline__ int ld_vol(const int* p) {
    int v;
    asm volatile("ld.volatile.global.s32 %0, [%1];" : "=r"(v) : "l"(p) : "memory");
    return v;
}

// ---------------------------------------------------------------------------
// Prep: zero counters/flags; decode x (auto-detect int32 vs int64; clamp).
// ---------------------------------------------------------------------------
__global__ void prep_kernel(const int* __restrict__ xr) {
    const int tid = blockIdx.x * blockDim.x + threadIdx.x;
    const int nt  = gridDim.x * blockDim.x;
    for (int i = tid; i < SEQ_T; i += nt) { g_cnt1[i] = 0; g_cnt2[i] = 0; }
    for (int i = tid; i < SEQ_T * NL1; i += nt) g_flagx[i] = 0;
    int odd_or = 0;
    #pragma unroll
    for (int i = 1; i < 32; i += 2) odd_or |= xr[i];
    const bool i64 = (odd_or == 0);   // int64 little-endian => odd words zero
    for (int i = tid; i < BAT * SEQ_T; i += nt) {
        int v = i64 ? (int)((const long long*)xr)[i] : xr[i];
        g_x[i] = min(max(v, 0), VOC - 1);
    }
}

// ---------------------------------------------------------------------------
// Merged scan kernel: 128 CTAs, 1/SM, all co-resident.
//   blockIdx < 64 : layer-1 (rec over W_hh0 + folded W_ih1 projection)
//   blockIdx >= 64: layer-2 (rec over W_hh1, consumes xw1 via per-CTA flag)
// smem (L1 role): hs[512][64] | wrec[8][512] | wproj[8][512] | esm[8][32]
// smem (L2 role): hs[512][64] | wrec[8][512]
// thread -> g = tid>>6 (half), b = tid&63; each thread owns 4 rows (4g..4g+3).
// ---------------------------------------------------------------------------
__global__ void __launch_bounds__(NT, 1) rnn_scan_kernel(
    const float* __restrict__ W_ih0,      // [HID][VOC]
    const float* __restrict__ b_ih0,
    const float* __restrict__ b_hh0,
    const float* __restrict__ W_hh0,      // [HID][HID]
    const float* __restrict__ W_ih1,      // [HID][HID]
    const float* __restrict__ b_ih1,
    const float* __restrict__ b_hh1,
    const float* __restrict__ W_hh1)      // [HID][HID]
{
    const int tid = threadIdx.x;
    const int g   = tid >> 6;             // 0..1
    const int b   = tid & 63;

    if (blockIdx.x < NL1) {
        // ================= Layer-1 role =================
        const int blk = blockIdx.x;
        const int i0  = blk * 8;
        float* hs    = smem;              // [512][64]
        float* wrec  = smem + HB;         // [8][512]
        float* wproj = wrec + 8 * HID;    // [8][512]
        float* esm   = wproj + 8 * HID;   // [8][32]

        for (int k = tid; k < 8 * HID; k += NT) {
            int r = k >> 9, c = k & (HID - 1);
            wrec[k]  = W_hh0[(i0 + r) * HID + c];
            wproj[k] = W_ih1[(i0 + r) * HID + c];
        }
        for (int k = tid; k < 8 * 32; k += NT) {
            int r = k >> 5, v = k & 31;
            esm[k] = (v < VOC)
                ? W_ih0[(i0 + r) * VOC + v] + b_ih0[i0 + r] + b_hh0[i0 + r]
                : 0.f;
        }
        const int rb = i0 + 4 * g;        // this thread's first row
        const float bp0 = b_ih1[rb + 0] + b_hh1[rb + 0];
        const float bp1 = b_ih1[rb + 1] + b_hh1[rb + 1];
        const float bp2 = b_ih1[rb + 2] + b_hh1[rb + 2];
        const float bp3 = b_ih1[rb + 3] + b_hh1[rb + 3];
        __syncthreads();

        const float* wbase = wrec  + (4 * g) * HID;
        const float* pbase = wproj + (4 * g) * HID;
        const unsigned int hs_u =
            (unsigned int)__cvta_generic_to_shared(hs) + tid * 16;
        const int* xb = g_x + b * SEQ_T;

        for (int t = 0; t < SEQ_T; t++) {
            float a0 = 0.f, a1 = 0.f, a2 = 0.f, a3 = 0.f;
            if (t > 0) {
                if (tid == 0) { while (ld_vol(&g_cnt1[t - 1]) < NL1) { } }
                __syncthreads();
                const char* gsrc = (const char*)(g_h1 + (t - 1) * HB) + tid * 16;
                #pragma unroll
                for (int c = 0; c < 4; c++) {
                    #pragma unroll
                    for (int k = 0; k < 16; k++)
                        cpa16(hs_u + c * 32768 + k * 2048, gsrc + c * 32768 + k * 2048);
                    CPA_COMMIT();
                }
                ull r0 = 0, r1 = 0, r2 = 0, r3 = 0;
                ull p0 = 0, p1 = 0, p2 = 0, p3 = 0;
                #pragma unroll
                for (int c = 0; c < 4; c++) {
                    if      (c == 0) CPA_WAIT(3);
                    else if (c == 1) CPA_WAIT(2);
                    else if (c == 2) CPA_WAIT(1);
                    else             CPA_WAIT(0);
                    __syncthreads();
                    const float* hc = hs + c * (128 * BAT);
                    const float* wa = wbase + c * 128;
                    const float* pa = pbase + c * 128;
                    #pragma unroll 2
                    for (int jj = 0; jj < 128; jj += 4) {
                        float h0 = hc[(jj + 0) * BAT + b];
                        float h1 = hc[(jj + 1) * BAT + b];
                        float h2 = hc[(jj + 2) * BAT + b];
                        float h3 = hc[(jj + 3) * BAT + b];
                        ull hA = pk2(h0, h1), hB = pk2(h2, h3);
                        ulonglong2 w0 = *(const ulonglong2*)(wa + 0 * HID + jj);
                        ulonglong2 w1 = *(const ulonglong2*)(wa + 1 * HID + jj);
                        ulonglong2 w2 = *(const ulonglong2*)(wa + 2 * HID + jj);
                        ulonglong2 w3 = *(const ulonglong2*)(wa + 3 * HID + jj);
                        fma2(r0, w0.x, hA); fma2(r0, w0.y, hB);
                        fma2(r1, w1.x, hA); fma2(r1, w1.y, hB);
                        fma2(r2, w2.x, hA); fma2(r2, w2.y, hB);
                        fma2(r3, w3.x, hA); fma2(r3, w3.y, hB);
                        ulonglong2 q0 = *(const ulonglong2*)(pa + 0 * HID + jj);
                        ulonglong2 q1 = *(const ulonglong2*)(pa + 1 * HID + jj);
                        ulonglong2 q2 = *(const ulonglong2*)(pa + 2 * HID + jj);
                        ulonglong2 q3 = *(const ulonglong2*)(pa + 3 * HID + jj);
                        fma2(p0, q0.x, hA); fma2(p0, q0.y, hB);
                        fma2(p1, q1.x, hA); fma2(p1, q1.y, hB);
                        fma2(p2, q2.x, hA); fma2(p2, q2.y, hB);
                        fma2(p3, q3.x, hA); fma2(p3, q3.y, hB);
                    }
                }
                a0 = fold2(r0); a1 = fold2(r1); a2 = fold2(r2); a3 = fold2(r3);
                float* xw = g_xw1 + (t - 1) * HB + rb * BAT + b;
                xw[0 * BAT] = fold2(p0) + bp0;
                xw[1 * BAT] = fold2(p1) + bp1;
                xw[2 * BAT] = fold2(p2) + bp2;
                xw[3 * BAT] = fold2(p3) + bp3;
            }
            const int v = xb[t];
            float* hd = g_h1 + t * HB + rb * BAT + b;
            hd[0 * BAT] = tanhf(esm[(4 * g + 0) * 32 + v] + a0);
            hd[1 * BAT] = tanhf(esm[(4 * g + 1) * 32 + v] + a1);
            hd[2 * BAT] = tanhf(esm[(4 * g + 2) * 32 + v] + a2);
            hd[3 * BAT] = tanhf(esm[(4 * g + 3) * 32 + v] + a3);
            __syncthreads();
            if (tid == 0) {
                __threadfence();
                atomicAdd(&g_cnt1[t], 1);
                if (t > 0) atomicExch(&g_flagx[(t - 1) * NL1 + blk], 1);
            }
        }

        // Epilogue: projection of h1[T-1] -> xw1[T-1].
        if (tid == 0) { while (ld_vol(&g_cnt1[SEQ_T - 1]) < NL1) { } }
        __syncthreads();
        {
            const float4* src = (const float4*)(g_h1 + (SEQ_T - 1) * HB);
            float4*       dst = (float4*)hs;
            #pragma unroll 8
            for (int m = 0; m < (HB / 4) / NT; m++)
                dst[tid + m * NT] = __ldcg(src + tid + m * NT);
            __syncthreads();
            ull p0 = 0, p1 = 0, p2 = 0, p3 = 0;
            #pragma unroll 2
            for (int j = 0; j < HID; j += 4) {
                float h0 = hs[(j + 0) * BAT + b];
                float h1 = hs[(j + 1) * BAT + b];
                float h2 = hs[(j + 2) * BAT + b];
                float h3 = hs[(j + 3) * BAT + b];
                ull hA = pk2(h0, h1), hB = pk2(h2, h3);
                ulonglong2 q0 = *(const ulonglong2*)(pbase + 0 * HID + j);
                ulonglong2 q1 = *(const ulonglong2*)(pbase + 1 * HID + j);
                ulonglong2 q2 = *(const ulonglong2*)(pbase + 2 * HID + j);
                ulonglong2 q3 = *(const ulonglong2*)(pbase + 3 * HID + j);
                fma2(p0, q0.x, hA); fma2(p0, q0.y, hB);
                fma2(p1, q1.x, hA); fma2(p1, q1.y, hB);
                fma2(p2, q2.x, hA); fma2(p2, q2.y, hB);
                fma2(p3, q3.x, hA); fma2(p3, q3.y, hB);
            }
            float* xw = g_xw1 + (SEQ_T - 1) * HB + rb * BAT + b;
            xw[0 * BAT] = fold2(p0) + bp0;
            xw[1 * BAT] = fold2(p1) + bp1;
            xw[2 * BAT] = fold2(p2) + bp2;
            xw[3 * BAT] = fold2(p3) + bp3;
            __syncthreads();
            if (tid == 0) {
                __threadfence();
                atomicExch(&g_flagx[(SEQ_T - 1) * NL1 + blk], 1);
            }
        }
    } else {
        // ================= Layer-2 role =================
        const int blk2 = blockIdx.x - NL1;
        const int i0   = blk2 * 8;
        float* hs   = smem;               // [512][64]
        float* wrec = smem + HB;          // [8][512]

        for (int k = tid; k < 8 * HID; k += NT) {
            int r = k >> 9, c = k & (HID - 1);
            wrec[k] = W_hh1[(i0 + r) * HID + c];
        }
        __syncthreads();

        const int rb = i0 + 4 * g;
        const float* wbase = wrec + (4 * g) * HID;
        const unsigned int hs_u =
            (unsigned int)__cvta_generic_to_shared(hs) + tid * 16;

        for (int u = 0; u < SEQ_T; u++) {
            float a0 = 0.f, a1 = 0.f, a2 = 0.f, a3 = 0.f;
            if (u > 0) {
                if (tid == 0) { while (ld_vol(&g_cnt2[u - 1]) < NL1) { } }
                __syncthreads();
                const char* gsrc = (const char*)(g_h2 + (u - 1) * HB) + tid * 16;
                #pragma unroll
                for (int c = 0; c < 4; c++) {
                    #pragma unroll
                    for (int k = 0; k < 16; k++)
                        cpa16(hs_u + c * 32768 + k * 2048, gsrc + c * 32768 + k * 2048);
                    CPA_COMMIT();
                }
                ull r0 = 0, r1 = 0, r2 = 0, r3 = 0;
                #pragma unroll
                for (int c = 0; c < 4; c++) {
                    if      (c == 0) CPA_WAIT(3);
                    else if (c == 1) CPA_WAIT(2);
                    else if (c == 2) CPA_WAIT(1);
                    else             CPA_WAIT(0);
                    __syncthreads();
                    const float* hc = hs + c * (128 * BAT);
                    const float* wa = wbase + c * 128;
                    #pragma unroll 4
                    for (int jj = 0; jj < 128; jj += 4) {
                        float h0 = hc[(jj + 0) * BAT + b];
                        float h1 = hc[(jj + 1) * BAT + b];
                        float h2 = hc[(jj + 2) * BAT + b];
                        float h3 = hc[(jj + 3) * BAT + b];
                        ull hA = pk2(h0, h1), hB = pk2(h2, h3);
                        ulonglong2 w0 = *(const ulonglong2*)(wa + 0 * HID + jj);
                        ulonglong2 w1 = *(const ulonglong2*)(wa + 1 * HID + jj);
                        ulonglong2 w2 = *(const ulonglong2*)(wa + 2 * HID + jj);
                        ulonglong2 w3 = *(const ulonglong2*)(wa + 3 * HID + jj);
                        fma2(r0, w0.x, hA); fma2(r0, w0.y, hB);
                        fma2(r1, w1.x, hA); fma2(r1, w1.y, hB);
                        fma2(r2, w2.x, hA); fma2(r2, w2.y, hB);
                        fma2(r3, w3.x, hA); fma2(r3, w3.y, hB);
                    }
                }
                a0 = fold2(r0); a1 = fold2(r1); a2 = fold2(r2); a3 = fold2(r3);
            }
            // Wait only for OUR xw1 slice producer (L1-CTA blk2).
            if (tid == 0) { while (ld_vol(&g_flagx[u * NL1 + blk2]) == 0) { } }
            __syncthreads();
            const float* xs = g_xw1 + u * HB + rb * BAT + b;
            float xa0 = __ldcg(xs + 0 * BAT);
            float xa1 = __ldcg(xs + 1 * BAT);
            float xa2 = __ldcg(xs + 2 * BAT);
            float xa3 = __ldcg(xs + 3 * BAT);
            float* hd = g_h2 + u * HB + rb * BAT + b;
            hd[0 * BAT] = tanhf(xa0 + a0);
            hd[1 * BAT] = tanhf(xa1 + a1);
            hd[2 * BAT] = tanhf(xa2 + a2);
            hd[3 * BAT] = tanhf(xa3 + a3);
            __syncthreads();
            if (tid == 0) {
                __threadfence();
                atomicAdd(&g_cnt2[u], 1);
            }
        }
    }
}

// ---------------------------------------------------------------------------
// Output: out[b][o] = sum_h W_out[o][h] * h2[T-1][h][b] + b_out[o].
// ---------------------------------------------------------------------------
__global__ void __launch_bounds__(NTO) out_kernel(
    const float* __restrict__ W_out,
    const float* __restrict__ b_out,
    float* __restrict__ out)
{
    float* hs  = smem;                    // [512][64]
    float* wsm = smem + HB;               // [4][512]

    const int tid = threadIdx.x;
    const int il  = tid >> 6;
    const int b   = tid & 63;
    const int o0  = blockIdx.x * 4;

    for (int k = tid; k < 4 * HID; k += NTO) {
        int r = k >> 9, c = k & (HID - 1);
        wsm[k] = W_out[(o0 + r) * HID + c];
    }
    {
        const float4* src = (const float4*)(g_h2 + (SEQ_T - 1) * HB);
        float4*       dst = (float4*)hs;
        #pragma unroll 8
        for (int m = 0; m < (HB / 4) / NTO; m++)
            dst[tid + m * NTO] = src[tid + m * NTO];
    }
    __syncthreads();

    const float* wr = wsm + il * HID;
    float ar = 0.f;
    #pragma unroll 4
    for (int j = 0; j < HID; j += 4) {
        float4 w4 = *(const float4*)(wr + j);
        ar = fmaf(w4.x, hs[(j + 0) * BAT + b], ar);
        ar = fmaf(w4.y, hs[(j + 1) * BAT + b], ar);
        ar = fmaf(w4.z, hs[(j + 2) * BAT + b], ar);
        ar = fmaf(w4.w, hs[(j + 3) * BAT + b], ar);
    }
    out[b * NOUT + (o0 + il)] = ar + b_out[o0 + il];
}

// ---------------------------------------------------------------------------
extern "C" void kernel_launch(void* const* d_in, const int* in_sizes, int n_in,
                              void* d_out, int out_size)
{
    const int*   x_raw = (const int*)d_in[0];   // int32 OR int64 (auto-detect)
    const float* W_ih0 = (const float*)d_in[1];
    const float* W_hh0 = (const float*)d_in[2];
    const float* b_ih0 = (const float*)d_in[3];
    const float* b_hh0 = (const float*)d_in[4];
    const float* W_ih1 = (const float*)d_in[5];
    const float* W_hh1 = (const float*)d_in[6];
    const float* b_ih1 = (const float*)d_in[7];
    const float* b_hh1 = (const float*)d_in[8];
    const float* W_out = (const float*)d_in[9];
    const float* b_out = (const float*)d_in[10];
    float* out         = (float*)d_out;

    // L1 role smem: hs(32768) + wrec(4096) + wproj(4096) + esm(256) floats
    const size_t s1 = (size_t)(HB + 8 * HID + 8 * HID + 256) * sizeof(float); // 164864
    const size_t s3 = (size_t)(HB + 4 * HID) * sizeof(float);                 // 139264

    cudaFuncSetAttribute(rnn_scan_kernel, cudaFuncAttributeMaxDynamicSharedMemorySize, (int)s1);
    cudaFuncSetAttribute(out_kernel,      cudaFuncAttributeMaxDynamicSharedMemorySize, (int)s3);

    prep_kernel<<<64, 512>>>(x_raw);
    rnn_scan_kernel<<<2 * NL1, NT, s1>>>(W_ih0, b_ih0, b_hh0, W_hh0,
                                         W_ih1, b_ih1, b_hh1, W_hh1);
    out_kernel<<<(NOUT + 3) / 4, NTO, s3>>>(W_out, b_out, out);
}